// round 13
// baseline (speedup 1.0000x reference)
#include <cuda_runtime.h>
#include <cuda_fp16.h>
#include <cuda_bf16.h>
#include <cstdint>
#include <math.h>

#define B_ 4
#define N_ 1024
#define M_ 1024
#define D_ 512
#define EPS_F 0.1f
#define INV_EPS 10.0f
#define THRESH_F 0.1f
#define LOG_MU -6.9314616f
#define MU_VAL (1.0f/1024.0f + 1e-8f)
#define NITER 20
#define GRID_P 148
#define SINK_T 1024
#define SINK_W (GRID_P * (SINK_T / 32))

// ---------------- scratch (no runtime allocation allowed) ----------------
__device__ __nv_bfloat16 g_Ebf [B_*N_*M_];   // bf16 exp(-C/eps), row-major
__device__ __nv_bfloat16 g_ETbf[B_*N_*M_];   // bf16 transpose
__device__ __half g_xh[B_*N_*D_];
__device__ __half g_yh[B_*M_*D_];
__device__ float g_nx[B_*N_], g_ny[B_*M_];
__device__ float g_u[B_*N_], g_aexp[B_*N_], g_bexp[B_*M_];
__device__ float g_errbuf[B_*N_], g_rowsum[B_*N_];
__device__ int g_cnt;
__device__ int g_gen;

// ---------------- helpers ----------------
__device__ __forceinline__ uint32_t smem_u32(const void* p) {
    uint32_t a;
    asm("{ .reg .u64 t; cvta.to.shared.u64 t, %1; cvt.u32.u64 %0, t; }"
        : "=r"(a) : "l"(p));
    return a;
}

__device__ __forceinline__ void ldsm_x4(uint32_t& r0, uint32_t& r1,
                                        uint32_t& r2, uint32_t& r3, uint32_t addr) {
    asm volatile("ldmatrix.sync.aligned.m8n8.x4.shared.b16 {%0,%1,%2,%3}, [%4];"
        : "=r"(r0), "=r"(r1), "=r"(r2), "=r"(r3) : "r"(addr));
}

__device__ __forceinline__ void mma16816(float* d, const uint32_t* a, const uint32_t* b) {
    asm volatile("mma.sync.aligned.m16n8k16.row.col.f32.f16.f16.f32 "
        "{%0,%1,%2,%3}, {%4,%5,%6,%7}, {%8,%9}, {%0,%1,%2,%3};"
        : "+f"(d[0]), "+f"(d[1]), "+f"(d[2]), "+f"(d[3])
        : "r"(a[0]), "r"(a[1]), "r"(a[2]), "r"(a[3]), "r"(b[0]), "r"(b[1]));
}

#define CP_ASYNC16(dst, src) \
    asm volatile("cp.async.cg.shared.global [%0], [%1], 16;" \
                 :: "r"(dst), "l"(src) : "memory")
#define CP_COMMIT() asm volatile("cp.async.commit_group;" ::: "memory")
#define CP_WAIT1()  asm volatile("cp.async.wait_group 1;" ::: "memory")
#define CP_WAIT0()  asm volatile("cp.async.wait_group 0;" ::: "memory")

// grid sync: acq_rel atomic arrival + acquire poll
__device__ __forceinline__ void grid_sync_dev() {
    __syncthreads();
    if (threadIdx.x == 0) {
        int gen;
        asm volatile("ld.global.s32 %0, [%1];" : "=r"(gen) : "l"(&g_gen) : "memory");
        int prev;
        asm volatile("atom.acq_rel.gpu.global.add.s32 %0, [%1], %2;"
                     : "=r"(prev) : "l"(&g_cnt), "r"(1) : "memory");
        if (prev == GRID_P - 1) {
            asm volatile("st.global.s32 [%0], %1;" :: "l"(&g_cnt), "r"(0) : "memory");
            asm volatile("st.release.gpu.global.s32 [%0], %1;"
                         :: "l"(&g_gen), "r"(gen + 1) : "memory");
        } else {
            int cur;
            do {
                asm volatile("ld.acquire.gpu.global.s32 %0, [%1];"
                             : "=r"(cur) : "l"(&g_gen) : "memory");
            } while (cur == gen);
        }
    }
    __syncthreads();
}

// dot over one bf16 row (1024 elems = 128 uint4) with fp32 weights
__device__ __forceinline__ float dot_bf_row(const uint4* erow, const float4* w, int lane) {
    float s = 0.f;
    #pragma unroll
    for (int p = 0; p < 4; p++) {
        uint4 e = erow[p * 32 + lane];
        float4 w0 = w[(p * 32 + lane) * 2];
        float4 w1 = w[(p * 32 + lane) * 2 + 1];
        float2 f0 = __bfloat1622float2(*(__nv_bfloat162*)&e.x);
        float2 f1 = __bfloat1622float2(*(__nv_bfloat162*)&e.y);
        float2 f2 = __bfloat1622float2(*(__nv_bfloat162*)&e.z);
        float2 f3 = __bfloat1622float2(*(__nv_bfloat162*)&e.w);
        s += f0.x * w0.x + f0.y * w0.y + f1.x * w0.z + f1.y * w0.w
           + f2.x * w1.x + f2.y * w1.y + f3.x * w1.z + f3.y * w1.w;
    }
    #pragma unroll
    for (int o = 16; o; o >>= 1) s += __shfl_down_sync(0xffffffffu, s, o);
    return s;
}

// ---------------- fused persistent kernel: prep + gemm + sinkhorn ----------
#define GS_STAGE 32768            // A 16KB + B 16KB per stage
#define FUSED_SMEM (2 * GS_STAGE) // 64KB dynamic
#define ST_S 136                  // bf16 staging stride per column

__global__ __launch_bounds__(SINK_T, 1)
void fused_kernel(const float* __restrict__ x, const float* __restrict__ y,
                  const float* __restrict__ nu, float* __restrict__ out) {
    extern __shared__ char smem[];
    const int t = threadIdx.x, wid = t >> 5, lane = t & 31;
    const int wgid = blockIdx.x * 32 + wid;      // global warp id (0..4735)
    __shared__ float red[32];
    __shared__ float redfull[SINK_T];
    uint32_t sb = smem_u32(smem);

    // ===== phase 0: norms + fp16 convert (1 row/warp) + state init =====
    {
        int gid = blockIdx.x * SINK_T + t;
        if (gid < B_ * M_) { g_bexp[gid] = 1.0f; g_u[gid] = 0.0f; }
    }
    for (int row = wgid; row < 2 * B_ * N_; row += SINK_W) {
        const float* src; float* nrm; __half* dst; int r;
        if (row < B_ * N_) { src = x; r = row;            nrm = g_nx; dst = g_xh; }
        else               { src = y; r = row - B_ * N_;  nrm = g_ny; dst = g_yh; }
        const float4* p = (const float4*)(src + (size_t)r * D_);
        float4 a[4];
        #pragma unroll
        for (int q = 0; q < 4; q++) a[q] = p[lane + q * 32];
        uint2* drow = (uint2*)(dst + (size_t)r * D_);
        float s = 0.f;
        #pragma unroll
        for (int q = 0; q < 4; q++) {
            s += a[q].x*a[q].x + a[q].y*a[q].y + a[q].z*a[q].z + a[q].w*a[q].w;
            __half2 h0 = __floats2half2_rn(a[q].x, a[q].y);
            __half2 h1 = __floats2half2_rn(a[q].z, a[q].w);
            uint2 pk;
            pk.x = *(const uint32_t*)&h0;
            pk.y = *(const uint32_t*)&h1;
            drow[lane + q * 32] = pk;
        }
        #pragma unroll
        for (int o = 16; o; o >>= 1) s += __shfl_down_sync(0xffffffffu, s, o);
        if (lane == 0) nrm[r] = sqrtf(s);
    }
    grid_sync_dev();

    // ===== phase 1: fp16 GEMM + exp epilogue, 128x128 tiles, grid-stride ====
    // warp layout: 8 m-groups (wid>>2) x 4 n-groups (wid&3); warp tile 16x32.
    {
        const int wm = (wid >> 2) * 16;
        const int wn = (wid & 3) * 32;
        for (int tI = blockIdx.x; tI < 256; tI += GRID_P) {
            const int jt = tI & 7, it = (tI >> 3) & 7, b = tI >> 6;
            const int i0 = it * 128, j0 = jt * 128;
            const __half* Axh = g_xh + ((size_t)b * N_ + i0) * D_;
            const __half* Byh = g_yh + ((size_t)b * M_ + j0) * D_;

            auto stage_load = [&](int c, int s) {
                uint32_t tb = sb + s * GS_STAGE;
                {   // A: 1024 chunks, one per thread
                    int row = t >> 3, cc = t & 7;
                    uint32_t off = row * 128 + ((cc ^ (row & 7)) << 4);
                    const __half* g = Axh + (size_t)row * D_ + c * 64 + cc * 8;
                    CP_ASYNC16(tb + off, (const void*)__cvta_generic_to_global(g));
                }
                {   // B: 1024 chunks, one per thread
                    int row = t >> 3, cc = t & 7;
                    uint32_t off = row * 128 + ((cc ^ (row & 7)) << 4);
                    const __half* g = Byh + (size_t)row * D_ + c * 64 + cc * 8;
                    CP_ASYNC16(tb + 16384 + off, (const void*)__cvta_generic_to_global(g));
                }
            };

            float acc[4][4];
            #pragma unroll
            for (int nf = 0; nf < 4; nf++)
                #pragma unroll
                for (int q = 0; q < 4; q++) acc[nf][q] = 0.f;

            stage_load(0, 0);
            CP_COMMIT();

            for (int c = 0; c < 8; c++) {
                if (c < 7) { stage_load(c + 1, (c + 1) & 1); CP_COMMIT(); CP_WAIT1(); }
                else       { CP_WAIT0(); }
                __syncthreads();

                uint32_t base = sb + (c & 1) * GS_STAGE;
                #pragma unroll
                for (int kk = 0; kk < 4; kk++) {
                    uint32_t ah[4], bh[4][2];
                    {
                        int row = wm + (lane & 15);
                        int seg = kk * 2 + (lane >> 4);
                        uint32_t ad = base + row * 128 + ((seg ^ (row & 7)) << 4);
                        ldsm_x4(ah[0], ah[1], ah[2], ah[3], ad);
                    }
                    #pragma unroll
                    for (int np = 0; np < 2; np++) {
                        int row = wn + np * 16 + (lane >> 4) * 8 + (lane & 7);
                        int seg = kk * 2 + ((lane >> 3) & 1);
                        uint32_t ad = base + 16384 + row * 128 + ((seg ^ (row & 7)) << 4);
                        ldsm_x4(bh[np*2][0], bh[np*2][1], bh[np*2+1][0], bh[np*2+1][1], ad);
                    }
                    #pragma unroll
                    for (int nf = 0; nf < 4; nf++)
                        mma16816(acc[nf], ah, bh[nf]);
                }
                __syncthreads();
            }

            // epilogue: E = exp(-C/eps) -> bf16; stage transposed for ET
            __nv_bfloat16* st16 = (__nv_bfloat16*)smem;   // 128 x ST_S bf16
            {
                int lr0 = wm + (lane >> 2);
                int r0 = i0 + lr0;
                float nx0 = g_nx[b * N_ + r0];
                float nx1 = g_nx[b * N_ + r0 + 8];
                #pragma unroll
                for (int nf = 0; nf < 4; nf++) {
                    int lc0 = wn + nf * 8 + (lane & 3) * 2;
                    int c0 = j0 + lc0;
                    float ny0 = g_ny[b * M_ + c0];
                    float ny1 = g_ny[b * M_ + c0 + 1];
                    const float* a = acc[nf];
                    float C00 = 1.f - a[0] / fmaxf(nx0 * ny0, 1e-8f);
                    float C01 = 1.f - a[1] / fmaxf(nx0 * ny1, 1e-8f);
                    float C10 = 1.f - a[2] / fmaxf(nx1 * ny0, 1e-8f);
                    float C11 = 1.f - a[3] / fmaxf(nx1 * ny1, 1e-8f);
                    __nv_bfloat16 e00 = __float2bfloat16(__expf(-INV_EPS * C00));
                    __nv_bfloat16 e01 = __float2bfloat16(__expf(-INV_EPS * C01));
                    __nv_bfloat16 e10 = __float2bfloat16(__expf(-INV_EPS * C10));
                    __nv_bfloat16 e11 = __float2bfloat16(__expf(-INV_EPS * C11));
                    size_t ro0 = ((size_t)b * N_ + r0) * M_ + c0;
                    size_t ro1 = ((size_t)b * N_ + r0 + 8) * M_ + c0;
                    *(__nv_bfloat162*)(g_Ebf + ro0) = __halves2bfloat162(e00, e01);
                    *(__nv_bfloat162*)(g_Ebf + ro1) = __halves2bfloat162(e10, e11);
                    st16[lc0 * ST_S + lr0]           = e00;
                    st16[(lc0 + 1) * ST_S + lr0]     = e01;
                    st16[lc0 * ST_S + lr0 + 8]       = e10;
                    st16[(lc0 + 1) * ST_S + lr0 + 8] = e11;
                }
            }
            __syncthreads();
            // ET tile: 128 rows (global cols j0..j0+127), each 128 bf16 at i0
            {
                int jj = t >> 3;                    // 0..127
                int part = (t & 7) * 16;            // 16 bf16 = 32B
                __nv_bfloat16* dst = g_ETbf + ((size_t)b * M_ + j0 + jj) * N_ + i0 + part;
                const __nv_bfloat16* srcrow = st16 + jj * ST_S + part;
                *(uint4*)(dst)     = *(const uint4*)(srcrow);
                *(uint4*)(dst + 8) = *(const uint4*)(srcrow + 8);
            }
            __syncthreads();   // smem reused by next tile's stage 0
        }
    }
    grid_sync_dev();

    // ===== phase 2: Sinkhorn loop =====
    for (int it = 0; it < NITER; it++) {
        for (int r = wgid; r < B_ * N_; r += SINK_W) {
            int b = r >> 10;
            float s = dot_bf_row((const uint4*)(g_Ebf + (size_t)r * M_),
                                 (const float4*)(g_bexp + (b << 10)), lane);
            if (lane == 0) {
                float u_new = EPS_F * (LOG_MU - __logf(s));
                g_errbuf[r] = fabsf(u_new - g_u[r]);
                g_u[r] = u_new;
                g_aexp[r] = MU_VAL / s;
            }
        }
        grid_sync_dev();   // publishes g_aexp AND g_errbuf

        // err reduction (shuffle-based; identical in every CTA)
        float es = g_errbuf[t] + g_errbuf[t + 1024]
                 + g_errbuf[t + 2048] + g_errbuf[t + 3072];
        #pragma unroll
        for (int o = 16; o; o >>= 1) es += __shfl_down_sync(0xffffffffu, es, o);
        if (lane == 0) red[wid] = es;
        __syncthreads();
        if (wid == 0) {
            float v = red[lane];
            #pragma unroll
            for (int o = 16; o; o >>= 1) v += __shfl_down_sync(0xffffffffu, v, o);
            if (lane == 0) red[0] = v;
        }
        __syncthreads();
        float errv = red[0];

        for (int c = wgid; c < B_ * M_; c += SINK_W) {
            int b = c >> 10;
            float s = dot_bf_row((const uint4*)(g_ETbf + (size_t)c * N_),
                                 (const float4*)(g_aexp + (b << 10)), lane);
            if (lane == 0)
                g_bexp[c] = (__ldg(&nu[c]) + 1e-8f) / s;
        }
        grid_sync_dev();   // publishes g_bexp; fences errbuf from next writer

        if (errv * 0.25f < THRESH_F) break;   // identical errv in all CTAs
    }

    // final cost: sum_i aexp_i * (sum_j E_ij*bexp_j*C_ij), C = -eps*ln(E)
    for (int r = wgid; r < B_ * N_; r += SINK_W) {
        int b = r >> 10;
        const uint4* erow = (const uint4*)(g_Ebf + (size_t)r * M_);
        const float4* w = (const float4*)(g_bexp + (b << 10));
        float s = 0.f;
        #pragma unroll
        for (int p = 0; p < 4; p++) {
            uint4 e = erow[p * 32 + lane];
            float4 w0 = w[(p * 32 + lane) * 2];
            float4 w1 = w[(p * 32 + lane) * 2 + 1];
            float2 f0 = __bfloat1622float2(*(__nv_bfloat162*)&e.x);
            float2 f1 = __bfloat1622float2(*(__nv_bfloat162*)&e.y);
            float2 f2 = __bfloat1622float2(*(__nv_bfloat162*)&e.z);
            float2 f3 = __bfloat1622float2(*(__nv_bfloat162*)&e.w);
            s += f0.x * w0.x * __logf(f0.x) + f0.y * w0.y * __logf(f0.y)
               + f1.x * w0.z * __logf(f1.x) + f1.y * w0.w * __logf(f1.y)
               + f2.x * w1.x * __logf(f2.x) + f2.y * w1.y * __logf(f2.y)
               + f3.x * w1.z * __logf(f3.x) + f3.y * w1.w * __logf(f3.y);
        }
        #pragma unroll
        for (int o = 16; o; o >>= 1) s += __shfl_down_sync(0xffffffffu, s, o);
        if (lane == 0) g_rowsum[r] = g_aexp[r] * s * (-EPS_F);
    }
    grid_sync_dev();
    if (blockIdx.x < B_) {
        int b = blockIdx.x;
        redfull[t] = g_rowsum[(b << 10) + t];
        __syncthreads();
        for (int o = 512; o; o >>= 1) {
            if (t < o) redfull[t] += redfull[t + o];
            __syncthreads();
        }
        if (t == 0) out[b] = redfull[0];
    }
}

// ---------------- launch ----------------
extern "C" void kernel_launch(void* const* d_in, const int* in_sizes, int n_in,
                              void* d_out, int out_size) {
    const float* x  = (const float*)d_in[0];
    const float* y  = (const float*)d_in[1];
    const float* nu = (const float*)d_in[2];
    float* out = (float*)d_out;

    cudaFuncSetAttribute(fused_kernel,
                         cudaFuncAttributeMaxDynamicSharedMemorySize, FUSED_SMEM);

    fused_kernel<<<GRID_P, SINK_T, FUSED_SMEM>>>(x, y, nu, out);
}

// round 14
// speedup vs baseline: 1.0972x; 1.0972x over previous
#include <cuda_runtime.h>
#include <cuda_fp16.h>
#include <cuda_bf16.h>
#include <cstdint>
#include <math.h>

#define B_ 4
#define N_ 1024
#define M_ 1024
#define D_ 512
#define EPS_F 0.1f
#define INV_EPS 10.0f
#define THRESH_F 0.1f
#define LOG_MU -6.9314616f
#define MU_VAL (1.0f/1024.0f + 1e-8f)
#define NITER 20
#define GRID_P 148
#define SINK_T 1024
#define SINK_W (GRID_P * (SINK_T / 32))

// ---------------- scratch (no runtime allocation allowed) ----------------
__device__ __nv_bfloat16 g_Ebf [B_*N_*M_];   // bf16 exp(-C/eps), row-major
__device__ __nv_bfloat16 g_ETbf[B_*N_*M_];   // bf16 transpose
__device__ __half g_xh[B_*N_*D_];
__device__ __half g_yh[B_*M_*D_];
__device__ float g_nx[B_*N_], g_ny[B_*M_];
__device__ float g_u[B_*N_], g_aexp[B_*N_], g_bexp[B_*M_];
__device__ float g_errbuf[B_*N_], g_rowsum[B_*N_];
__device__ int g_cnt;
__device__ int g_gen;

// ---------------- helpers ----------------
__device__ __forceinline__ uint32_t smem_u32(const void* p) {
    uint32_t a;
    asm("{ .reg .u64 t; cvta.to.shared.u64 t, %1; cvt.u32.u64 %0, t; }"
        : "=r"(a) : "l"(p));
    return a;
}

__device__ __forceinline__ void ldsm_x4(uint32_t& r0, uint32_t& r1,
                                        uint32_t& r2, uint32_t& r3, uint32_t addr) {
    asm volatile("ldmatrix.sync.aligned.m8n8.x4.shared.b16 {%0,%1,%2,%3}, [%4];"
        : "=r"(r0), "=r"(r1), "=r"(r2), "=r"(r3) : "r"(addr));
}

__device__ __forceinline__ void mma16816(float* d, const uint32_t* a, const uint32_t* b) {
    asm volatile("mma.sync.aligned.m16n8k16.row.col.f32.f16.f16.f32 "
        "{%0,%1,%2,%3}, {%4,%5,%6,%7}, {%8,%9}, {%0,%1,%2,%3};"
        : "+f"(d[0]), "+f"(d[1]), "+f"(d[2]), "+f"(d[3])
        : "r"(a[0]), "r"(a[1]), "r"(a[2]), "r"(a[3]), "r"(b[0]), "r"(b[1]));
}

#define CP_ASYNC16(dst, src) \
    asm volatile("cp.async.cg.shared.global [%0], [%1], 16;" \
                 :: "r"(dst), "l"(src) : "memory")
#define CP_COMMIT() asm volatile("cp.async.commit_group;" ::: "memory")
#define CP_WAIT1()  asm volatile("cp.async.wait_group 1;" ::: "memory")
#define CP_WAIT0()  asm volatile("cp.async.wait_group 0;" ::: "memory")

// ---------------- norms + fp16 convert (warp-per-row, single launch) -------
__global__ __launch_bounds__(256)
void normsplit_kernel(const float* __restrict__ x, const float* __restrict__ y) {
    int gw = (blockIdx.x * 256 + threadIdx.x) >> 5;   // global warp = row id
    int lane = threadIdx.x & 31;
    if (gw >= 2 * B_ * N_) return;
    const float* src; float* nrm; __half* dst; int row;
    if (gw < B_ * N_) { src = x; row = gw;            nrm = g_nx; dst = g_xh; }
    else              { src = y; row = gw - B_ * N_;  nrm = g_ny; dst = g_yh; }

    const float4* p = (const float4*)(src + (size_t)row * D_);
    uint2* drow = (uint2*)(dst + (size_t)row * D_);
    float s = 0.f;
    #pragma unroll
    for (int q = 0; q < 4; q++) {
        float4 a = p[lane + q * 32];
        s += a.x*a.x + a.y*a.y + a.z*a.z + a.w*a.w;
        __half2 h0 = __floats2half2_rn(a.x, a.y);
        __half2 h1 = __floats2half2_rn(a.z, a.w);
        uint2 pk;
        pk.x = *(const uint32_t*)&h0;
        pk.y = *(const uint32_t*)&h1;
        drow[lane + q * 32] = pk;
    }
    #pragma unroll
    for (int o = 16; o; o >>= 1) s += __shfl_down_sync(0xffffffffu, s, o);
    if (lane == 0) nrm[row] = sqrtf(s);
}

// ---------------- mma.sync fp16 GEMM, 128x128 tiles, 2 CTAs/SM -------------
// stage layout: A @0 (16KB), B @16384 (16KB); 32KB/stage, 2 stages = 64KB/CTA.
#define GS_STAGE 32768
#define GEMM_SMEM (2 * GS_STAGE)
#define ST_S 136   // staging stride (bf16 elems per column; 16B-aligned)

__global__ __launch_bounds__(256, 2)
void gemm_mma_kernel() {
    extern __shared__ char smem[];
    const int tid = threadIdx.x;
    const int wid = tid >> 5, lane = tid & 31;
    const int b = blockIdx.z, i0 = blockIdx.y * 128, j0 = blockIdx.x * 128;
    const int wm = (wid >> 2) * 64;     // warp row offset (0 or 64)
    const int wn = (wid & 3) * 32;      // warp col offset (0..96)
    uint32_t sb = smem_u32(smem);

    const __half* Axh = g_xh + ((size_t)b * N_ + i0) * D_;
    const __half* Byh = g_yh + ((size_t)b * M_ + j0) * D_;

    auto stage_load = [&](int c, int s) {
        uint32_t tb = sb + s * GS_STAGE;
        #pragma unroll
        for (int q = 0; q < 4; q++) {
            int idx = q * 256 + tid;            // A: 1024 chunks
            int row = idx >> 3, cc = idx & 7;
            uint32_t off = row * 128 + ((cc ^ (row & 7)) << 4);
            const __half* g = Axh + (size_t)row * D_ + c * 64 + cc * 8;
            CP_ASYNC16(tb + off, (const void*)__cvta_generic_to_global(g));
        }
        #pragma unroll
        for (int q = 0; q < 4; q++) {
            int idx = q * 256 + tid;            // B: 1024 chunks
            int row = idx >> 3, cc = idx & 7;
            uint32_t off = row * 128 + ((cc ^ (row & 7)) << 4);
            const __half* g = Byh + (size_t)row * D_ + c * 64 + cc * 8;
            CP_ASYNC16(tb + 16384 + off, (const void*)__cvta_generic_to_global(g));
        }
    };

    float acc[4][4][4];
    #pragma unroll
    for (int mt = 0; mt < 4; mt++)
        #pragma unroll
        for (int nf = 0; nf < 4; nf++)
            #pragma unroll
            for (int q = 0; q < 4; q++) acc[mt][nf][q] = 0.f;

    stage_load(0, 0);
    CP_COMMIT();

    for (int c = 0; c < 8; c++) {
        if (c < 7) { stage_load(c + 1, (c + 1) & 1); CP_COMMIT(); CP_WAIT1(); }
        else       { CP_WAIT0(); }
        __syncthreads();

        uint32_t base = sb + (c & 1) * GS_STAGE;
        #pragma unroll
        for (int kk = 0; kk < 4; kk++) {
            uint32_t ah[4][4], bh[4][2];
            #pragma unroll
            for (int mt = 0; mt < 4; mt++) {
                int row = wm + mt * 16 + ((lane >> 3) & 1) * 8 + (lane & 7);
                int seg = kk * 2 + (lane >> 4);
                uint32_t ad = base + row * 128 + ((seg ^ (row & 7)) << 4);
                ldsm_x4(ah[mt][0], ah[mt][1], ah[mt][2], ah[mt][3], ad);
            }
            #pragma unroll
            for (int np = 0; np < 2; np++) {
                int row = wn + np * 16 + (lane >> 4) * 8 + (lane & 7);
                int seg = kk * 2 + ((lane >> 3) & 1);
                uint32_t ad = base + 16384 + row * 128 + ((seg ^ (row & 7)) << 4);
                ldsm_x4(bh[np*2][0], bh[np*2][1], bh[np*2+1][0], bh[np*2+1][1], ad);
            }
            #pragma unroll
            for (int mt = 0; mt < 4; mt++)
                #pragma unroll
                for (int nf = 0; nf < 4; nf++)
                    mma16816(acc[mt][nf], ah[mt], bh[nf]);
        }
        __syncthreads();
    }

    // epilogue: E = exp(-C/eps) -> bf16; stage E transposed in smem for ET.
    __nv_bfloat16* st16 = (__nv_bfloat16*)smem;   // 128 cols x ST_S = 34816 B
    #pragma unroll
    for (int mt = 0; mt < 4; mt++) {
        int lr0 = wm + mt * 16 + (lane >> 2);      // local row
        int r0 = i0 + lr0;
        float nx0 = g_nx[b * N_ + r0];
        float nx1 = g_nx[b * N_ + r0 + 8];
        #pragma unroll
        for (int nf = 0; nf < 4; nf++) {
            int lc0 = wn + nf * 8 + (lane & 3) * 2;
            int c0 = j0 + lc0;
            float ny0 = g_ny[b * M_ + c0];
            float ny1 = g_ny[b * M_ + c0 + 1];
            const float* a = acc[mt][nf];
            float C00 = 1.f - a[0] / fmaxf(nx0 * ny0, 1e-8f);
            float C01 = 1.f - a[1] / fmaxf(nx0 * ny1, 1e-8f);
            float C10 = 1.f - a[2] / fmaxf(nx1 * ny0, 1e-8f);
            float C11 = 1.f - a[3] / fmaxf(nx1 * ny1, 1e-8f);
            __nv_bfloat16 e00 = __float2bfloat16(__expf(-INV_EPS * C00));
            __nv_bfloat16 e01 = __float2bfloat16(__expf(-INV_EPS * C01));
            __nv_bfloat16 e10 = __float2bfloat16(__expf(-INV_EPS * C10));
            __nv_bfloat16 e11 = __float2bfloat16(__expf(-INV_EPS * C11));
            size_t ro0 = ((size_t)b * N_ + r0) * M_ + c0;
            size_t ro1 = ((size_t)b * N_ + r0 + 8) * M_ + c0;
            *(__nv_bfloat162*)(g_Ebf + ro0) = __halves2bfloat162(e00, e01);
            *(__nv_bfloat162*)(g_Ebf + ro1) = __halves2bfloat162(e10, e11);
            st16[lc0 * ST_S + lr0]           = e00;
            st16[(lc0 + 1) * ST_S + lr0]     = e01;
            st16[lc0 * ST_S + lr0 + 8]       = e10;
            st16[(lc0 + 1) * ST_S + lr0 + 8] = e11;
        }
    }
    __syncthreads();
    // ET tile: 128 rows (global cols j0..j0+127), each 128 bf16 at i0
    {
        int jj = tid >> 1;                  // 0..127
        int half = (tid & 1) * 64;          // 64 bf16 = 128B
        __nv_bfloat16* dst = g_ETbf + ((size_t)b * M_ + j0 + jj) * N_ + i0 + half;
        const __nv_bfloat16* srcrow = st16 + jj * ST_S + half;
        #pragma unroll
        for (int k = 0; k < 64; k += 8)
            *(uint4*)(dst + k) = *(const uint4*)(srcrow + k);
    }
}

// ---------------- persistent Sinkhorn kernel (1024 threads/CTA) ----------------
// cooperative-groups-style grid sync: acq_rel atomic arrival + acquire poll.
__device__ __forceinline__ void grid_sync_dev() {
    __syncthreads();
    if (threadIdx.x == 0) {
        int gen;
        asm volatile("ld.global.s32 %0, [%1];" : "=r"(gen) : "l"(&g_gen) : "memory");
        int prev;
        asm volatile("atom.acq_rel.gpu.global.add.s32 %0, [%1], %2;"
                     : "=r"(prev) : "l"(&g_cnt), "r"(1) : "memory");
        if (prev == GRID_P - 1) {
            asm volatile("st.global.s32 [%0], %1;" :: "l"(&g_cnt), "r"(0) : "memory");
            asm volatile("st.release.gpu.global.s32 [%0], %1;"
                         :: "l"(&g_gen), "r"(gen + 1) : "memory");
        } else {
            int cur;
            do {
                asm volatile("ld.acquire.gpu.global.s32 %0, [%1];"
                             : "=r"(cur) : "l"(&g_gen) : "memory");
            } while (cur == gen);
        }
    }
    __syncthreads();
}

// dot over one bf16 row (1024 elems = 128 uint4) with fp32 weights
__device__ __forceinline__ float dot_bf_row(const uint4* erow, const float4* w, int lane) {
    float s = 0.f;
    #pragma unroll
    for (int p = 0; p < 4; p++) {
        uint4 e = erow[p * 32 + lane];
        float4 w0 = w[(p * 32 + lane) * 2];
        float4 w1 = w[(p * 32 + lane) * 2 + 1];
        float2 f0 = __bfloat1622float2(*(__nv_bfloat162*)&e.x);
        float2 f1 = __bfloat1622float2(*(__nv_bfloat162*)&e.y);
        float2 f2 = __bfloat1622float2(*(__nv_bfloat162*)&e.z);
        float2 f3 = __bfloat1622float2(*(__nv_bfloat162*)&e.w);
        s += f0.x * w0.x + f0.y * w0.y + f1.x * w0.z + f1.y * w0.w
           + f2.x * w1.x + f2.y * w1.y + f3.x * w1.z + f3.y * w1.w;
    }
    #pragma unroll
    for (int o = 16; o; o >>= 1) s += __shfl_down_sync(0xffffffffu, s, o);
    return s;
}

__global__ __launch_bounds__(SINK_T)
void sinkhorn_kernel(const float* __restrict__ nu, float* __restrict__ out) {
    const int t = threadIdx.x, wid = t >> 5, lane = t & 31;
    const int wgid = blockIdx.x * (SINK_T / 32) + wid;   // 0..SINK_W-1
    __shared__ float red[32];
    __shared__ float redfull[SINK_T];

    {   // init: v=0 -> bexp=1, u=0
        int gid = blockIdx.x * SINK_T + t;
        if (gid < B_ * M_) { g_bexp[gid] = 1.0f; g_u[gid] = 0.0f; }
    }
    grid_sync_dev();

    for (int it = 0; it < NITER; it++) {
        // ---- u update (~1 row per warp) ----
        for (int r = wgid; r < B_ * N_; r += SINK_W) {
            int b = r >> 10;
            float s = dot_bf_row((const uint4*)(g_Ebf + (size_t)r * M_),
                                 (const float4*)(g_bexp + (b << 10)), lane);
            if (lane == 0) {
                float u_new = EPS_F * (LOG_MU - __logf(s));
                g_errbuf[r] = fabsf(u_new - g_u[r]);
                g_u[r] = u_new;
                g_aexp[r] = MU_VAL / s;
            }
        }
        grid_sync_dev();   // publishes g_aexp AND g_errbuf

        // ---- err reduction (shuffle-based; identical in every CTA) ----
        float es = g_errbuf[t] + g_errbuf[t + 1024]
                 + g_errbuf[t + 2048] + g_errbuf[t + 3072];
        #pragma unroll
        for (int o = 16; o; o >>= 1) es += __shfl_down_sync(0xffffffffu, es, o);
        if (lane == 0) red[wid] = es;
        __syncthreads();
        if (wid == 0) {
            float v = red[lane];
            #pragma unroll
            for (int o = 16; o; o >>= 1) v += __shfl_down_sync(0xffffffffu, v, o);
            if (lane == 0) red[0] = v;
        }
        __syncthreads();
        float errv = red[0];

        // ---- v update ----
        for (int c = wgid; c < B_ * M_; c += SINK_W) {
            int b = c >> 10;
            float s = dot_bf_row((const uint4*)(g_ETbf + (size_t)c * N_),
                                 (const float4*)(g_aexp + (b << 10)), lane);
            if (lane == 0)
                g_bexp[c] = (__ldg(&nu[c]) + 1e-8f) / s;
        }
        grid_sync_dev();   // publishes g_bexp; fences errbuf from next writer

        // done-freeze: all remaining reference iterations are exact no-ops
        if (errv * 0.25f < THRESH_F) break;   // identical errv in all CTAs
    }

    // final cost: sum_i aexp_i * (sum_j E_ij*bexp_j*C_ij), C = -eps*ln(E)
    for (int r = wgid; r < B_ * N_; r += SINK_W) {
        int b = r >> 10;
        const uint4* erow = (const uint4*)(g_Ebf + (size_t)r * M_);
        const float4* w = (const float4*)(g_bexp + (b << 10));
        float s = 0.f;
        #pragma unroll
        for (int p = 0; p < 4; p++) {
            uint4 e = erow[p * 32 + lane];
            float4 w0 = w[(p * 32 + lane) * 2];
            float4 w1 = w[(p * 32 + lane) * 2 + 1];
            float2 f0 = __bfloat1622float2(*(__nv_bfloat162*)&e.x);
            float2 f1 = __bfloat1622float2(*(__nv_bfloat162*)&e.y);
            float2 f2 = __bfloat1622float2(*(__nv_bfloat162*)&e.z);
            float2 f3 = __bfloat1622float2(*(__nv_bfloat162*)&e.w);
            s += f0.x * w0.x * __logf(f0.x) + f0.y * w0.y * __logf(f0.y)
               + f1.x * w0.z * __logf(f1.x) + f1.y * w0.w * __logf(f1.y)
               + f2.x * w1.x * __logf(f2.x) + f2.y * w1.y * __logf(f2.y)
               + f3.x * w1.z * __logf(f3.x) + f3.y * w1.w * __logf(f3.y);
        }
        #pragma unroll
        for (int o = 16; o; o >>= 1) s += __shfl_down_sync(0xffffffffu, s, o);
        if (lane == 0) g_rowsum[r] = g_aexp[r] * s * (-EPS_F);
    }
    grid_sync_dev();
    if (blockIdx.x < B_) {
        int b = blockIdx.x;
        redfull[t] = g_rowsum[(b << 10) + t];
        __syncthreads();
        for (int o = 512; o; o >>= 1) {
            if (t < o) redfull[t] += redfull[t + o];
            __syncthreads();
        }
        if (t == 0) out[b] = redfull[0];
    }
}

// ---------------- launch ----------------
extern "C" void kernel_launch(void* const* d_in, const int* in_sizes, int n_in,
                              void* d_out, int out_size) {
    const float* x  = (const float*)d_in[0];
    const float* y  = (const float*)d_in[1];
    const float* nu = (const float*)d_in[2];
    float* out = (float*)d_out;

    cudaFuncSetAttribute(gemm_mma_kernel,
                         cudaFuncAttributeMaxDynamicSharedMemorySize, GEMM_SMEM);

    normsplit_kernel<<<1024, 256>>>(x, y);

    gemm_mma_kernel<<<dim3(8, 8, 4), 256, GEMM_SMEM>>>();

    sinkhorn_kernel<<<GRID_P, SINK_T>>>(nu, out);
}